// round 12
// baseline (speedup 1.0000x reference)
#include <cuda_runtime.h>
#include <math.h>

#define B_    16
#define L_    400
#define T_    200
#define NMELS 80
#define ENC   512
#define PRE   256
#define QHD   1024
#define ATTN_ 128
#define NFILT 32
#define NBLK  148
#define NTHR  512
#define SMEM_BYTES 163840   // dLSTM packed staging: 8 pairs * 2560 * 8 B

typedef unsigned long long ull;

// ---- scratch (device globals; allocation forbidden) ----
__device__ __align__(16) float g_dec_ins[T_ * B_ * PRE];
__device__ __align__(16) float g_h1[B_ * T_ * PRE];
__device__ __align__(16) float g_pm[B_ * L_ * ATTN_];
__device__ __align__(16) float g_cl[B_ * L_ * NFILT];
__device__ __align__(16) float g_p[B_ * L_];          // exp(energy)
__device__ __align__(16) float g_psum[2][B_ * 8];     // per-tile partial sums
__device__ __align__(16) float g_pq[B_ * ATTN_];
__device__ __align__(16) float g_ctxraw[2][B_ * ENC]; // unnormalized context
__device__ __align__(16) float g_A[2][B_ * L_];       // cumulative attention
__device__ __align__(16) float g_qh[2][B_ * QHD];
__device__ __align__(16) float g_qc[B_ * QHD];
__device__ __align__(16) float g_dh[2][B_ * QHD];
__device__ __align__(16) float g_dc[B_ * QHD];
__device__ unsigned g_count;
__device__ unsigned g_gen;

// ---- f32x2 helpers ----
__device__ __forceinline__ ull f2bcast(float a) {
    ull r; asm("mov.b64 %0, {%1, %1};" : "=l"(r) : "f"(a)); return r;
}
__device__ __forceinline__ ull fma2(ull x, ull w, ull c) {
    ull d; asm("fma.rn.f32x2 %0, %1, %2, %3;" : "=l"(d) : "l"(x), "l"(w), "l"(c)); return d;
}
__device__ __forceinline__ ull add2(ull a, ull b) {
    ull d; asm("add.rn.f32x2 %0, %1, %2;" : "=l"(d) : "l"(a), "l"(b)); return d;
}
__device__ __forceinline__ float2 unpack2(ull v) {
    float2 f; asm("mov.b64 {%0, %1}, %2;" : "=f"(f.x), "=f"(f.y) : "l"(v)); return f;
}

// ---- software grid barrier (release fence only; consumers use __ldcg) ----
__device__ __forceinline__ void grid_sync() {
    __syncthreads();
    if (threadIdx.x == 0) {
        unsigned gen = __ldcg(&g_gen);
        __threadfence();
        if (atomicAdd(&g_count, 1u) == NBLK - 1) {
            g_count = 0u;
            __threadfence();
            atomicAdd(&g_gen, 1u);
        } else {
            while (__ldcg(&g_gen) == gen) __nanosleep(64);
        }
    }
    __syncthreads();
}

__device__ __forceinline__ float sigmoidf_(float z) { return 1.f / (1.f + expf(-z)); }

// ---- stage 16 batches into packed f32x2 smem: xs2[pair p][k], pair = (b=p, b=p+8) ----
__device__ __forceinline__ void stage2(float2* xs2, int Kf2, int coff,
                                       const float* __restrict__ src, int glen, int len) {
    int n4 = len >> 2;
    for (int idx = threadIdx.x; idx < 8 * n4; idx += NTHR) {
        int p = idx / n4, k4 = (idx - p * n4) << 2;
        float4 lo = __ldcg((const float4*)(src + (size_t)p * glen + k4));
        float4 hi = __ldcg((const float4*)(src + (size_t)(p + 8) * glen + k4));
        float2* d = xs2 + (size_t)p * Kf2 + coff + k4;
        *(float4*)(d)     = make_float4(lo.x, hi.x, lo.y, hi.y);
        *(float4*)(d + 2) = make_float4(lo.z, hi.z, lo.w, hi.w);
    }
}
__device__ __forceinline__ void stage2_scaled(float2* xs2, int Kf2, int coff,
                                              const float* __restrict__ src, int len,
                                              const float* sinv) {
    int n4 = len >> 2;
    for (int idx = threadIdx.x; idx < 8 * n4; idx += NTHR) {
        int p = idx / n4, k4 = (idx - p * n4) << 2;
        float sl = sinv[p], sh = sinv[p + 8];
        float4 lo = __ldcg((const float4*)(src + (size_t)p * len + k4));
        float4 hi = __ldcg((const float4*)(src + (size_t)(p + 8) * len + k4));
        float2* d = xs2 + (size_t)p * Kf2 + coff + k4;
        *(float4*)(d)     = make_float4(lo.x * sl, hi.x * sh, lo.y * sl, hi.y * sh);
        *(float4*)(d + 2) = make_float4(lo.z * sl, hi.z * sh, lo.w * sl, hi.w * sh);
    }
}
__device__ __forceinline__ void stage2_zero(float2* xs2, int Kf2, int coff, int len) {
    int n4 = len >> 2;
    float4 z = make_float4(0.f, 0.f, 0.f, 0.f);
    for (int idx = threadIdx.x; idx < 8 * n4; idx += NTHR) {
        int p = idx / n4, k4 = (idx - p * n4) << 2;
        float2* d = xs2 + (size_t)p * Kf2 + coff + k4;
        *(float4*)(d) = z; *(float4*)(d + 2) = z;
    }
}

// ---- f32x2 gemv, conflict-free: lane covers cols (2*lane, 2*lane+1) per 64-col iter.
// x via one LDS.128 per pair (contiguous 512B), weights via prefetched LDG.64 ----
template<int NC>
__device__ __forceinline__ void gemvf2c(const ull* __restrict__ xb, int Kf2,
                                        const float* __restrict__ w0,
                                        const float* __restrict__ w1,
                                        const float* __restrict__ w2,
                                        const float* __restrict__ w3,
                                        int lane, ull acc[4][8]) {
    int c0 = lane << 1;
    float2 wa = *(const float2*)(w0 + c0);
    float2 wb = *(const float2*)(w1 + c0);
    float2 wc = *(const float2*)(w2 + c0);
    float2 wd = *(const float2*)(w3 + c0);
    #pragma unroll
    for (int it = 0; it < NC; ++it) {
        float2 na, nb, nc2, nd;
        if (it + 1 < NC) {
            int cn = c0 + ((it + 1) << 6);
            na  = *(const float2*)(w0 + cn);
            nb  = *(const float2*)(w1 + cn);
            nc2 = *(const float2*)(w2 + cn);
            nd  = *(const float2*)(w3 + cn);
        } else {
            na = nb = nc2 = nd = make_float2(0.f, 0.f);
        }
        ull A0 = f2bcast(wa.x), A1 = f2bcast(wa.y);
        ull B0 = f2bcast(wb.x), B1 = f2bcast(wb.y);
        ull C0 = f2bcast(wc.x), C1 = f2bcast(wc.y);
        ull D0 = f2bcast(wd.x), D1 = f2bcast(wd.y);
        const ull* xp = xb + (it << 6) + c0;
        #pragma unroll
        for (int p = 0; p < 8; ++p) {
            longlong2 xv = *(const longlong2*)(xp + (size_t)p * Kf2);
            ull x0 = (ull)xv.x, x1 = (ull)xv.y;
            acc[0][p] = fma2(x0, A0, acc[0][p]);
            acc[1][p] = fma2(x0, B0, acc[1][p]);
            acc[2][p] = fma2(x0, C0, acc[2][p]);
            acc[3][p] = fma2(x0, D0, acc[3][p]);
            acc[0][p] = fma2(x1, A1, acc[0][p]);
            acc[1][p] = fma2(x1, B1, acc[1][p]);
            acc[2][p] = fma2(x1, C1, acc[2][p]);
            acc[3][p] = fma2(x1, D1, acc[3][p]);
        }
        wa = na; wb = nb; wc = nc2; wd = nd;
    }
}

// ---- LSTM phase: warp-pair per unit (lu = w>>1, K-half = w&1), all 4 gates ----
template<int NCIH, int NCHH>
__device__ __forceinline__ void lstm2(const float2* xs2, int Kf2, int kih, int ihHalf,
        const float* __restrict__ wih, const float* __restrict__ whh,
        const float* __restrict__ bih, const float* __restrict__ bhh,
        float* __restrict__ ho, float* __restrict__ cb, int u0, int nu, float2* shz2) {
    int tid = threadIdx.x, lane = tid & 31, w = tid >> 5;
    int lu = w >> 1, h = w & 1;
    if (lu < nu) {
        int u = u0 + lu;
        ull acc[4][8];
        #pragma unroll
        for (int g = 0; g < 4; ++g)
            #pragma unroll
            for (int p = 0; p < 8; ++p) acc[g][p] = 0ull;
        gemvf2c<NCIH>((const ull*)xs2 + h * ihHalf, Kf2,
                      wih + (size_t)(0 * 1024 + u) * kih + h * ihHalf,
                      wih + (size_t)(1 * 1024 + u) * kih + h * ihHalf,
                      wih + (size_t)(2 * 1024 + u) * kih + h * ihHalf,
                      wih + (size_t)(3 * 1024 + u) * kih + h * ihHalf, lane, acc);
        gemvf2c<NCHH>((const ull*)xs2 + kih + h * 512, Kf2,
                      whh + (size_t)(0 * 1024 + u) * QHD + h * 512,
                      whh + (size_t)(1 * 1024 + u) * QHD + h * 512,
                      whh + (size_t)(2 * 1024 + u) * QHD + h * 512,
                      whh + (size_t)(3 * 1024 + u) * QHD + h * 512, lane, acc);
        #pragma unroll
        for (int g = 0; g < 4; ++g)
            #pragma unroll
            for (int p = 0; p < 8; ++p) {
                ull v = acc[g][p];
                #pragma unroll
                for (int off = 16; off > 0; off >>= 1)
                    v = add2(v, __shfl_xor_sync(0xffffffffu, v, off));
                acc[g][p] = v;
            }
        if (lane == 0) {
            float2* dst = shz2 + (lu * 2 + h) * 32;
            #pragma unroll
            for (int g = 0; g < 4; ++g)
                #pragma unroll
                for (int p = 0; p < 8; ++p) dst[g * 8 + p] = unpack2(acc[g][p]);
        }
    }
    __syncthreads();
    if (tid < 16 * nu) {
        int b = tid & 15, ui = tid >> 4, u = u0 + ui;
        int p = b & 7, hi8 = b >> 3;
        float z[4];
        #pragma unroll
        for (int g = 0; g < 4; ++g) {
            float2 a = shz2[(ui * 2 + 0) * 32 + g * 8 + p];
            float2 c2 = shz2[(ui * 2 + 1) * 32 + g * 8 + p];
            z[g] = (hi8 ? a.y : a.x) + (hi8 ? c2.y : c2.x)
                 + bih[g * 1024 + u] + bhh[g * 1024 + u];
        }
        float cc = sigmoidf_(z[1]) * cb[b * 1024 + u] + sigmoidf_(z[0]) * tanhf(z[2]);
        cb[b * 1024 + u] = cc;
        ho[b * 1024 + u] = sigmoidf_(z[3]) * tanhf(cc);
    }
    __syncthreads();
}

// ---- pq: block covers (b = blk>>1, 64 rows) ----
__device__ __forceinline__ void pq_phase(const float* __restrict__ wq,
                                         const float* __restrict__ hq_all,
                                         int blk, float* dsh) {
    int tid = threadIdx.x, lane = tid & 31, w = tid >> 5;
    int b = blk >> 1, rbase = (blk & 1) * 64;
    for (int i = tid; i < QHD; i += NTHR) dsh[i] = __ldcg(hq_all + (size_t)b * QHD + i);
    __syncthreads();
    int l4 = lane << 2;
    for (int pass = 0; pass < 2; ++pass) {
        int r0 = rbase + pass * 32 + w * 2, r1 = r0 + 1;
        const float* w0 = wq + (size_t)r0 * QHD;
        const float* w1 = wq + (size_t)r1 * QHD;
        float s0 = 0.f, s1 = 0.f;
        for (int ch = 0; ch < 8; ++ch) {
            float4 a = *(const float4*)(w0 + (ch << 7) + l4);
            float4 c = *(const float4*)(w1 + (ch << 7) + l4);
            float4 xv = *(const float4*)(dsh + (ch << 7) + l4);
            s0 += a.x * xv.x + a.y * xv.y + a.z * xv.z + a.w * xv.w;
            s1 += c.x * xv.x + c.y * xv.y + c.z * xv.z + c.w * xv.w;
        }
        #pragma unroll
        for (int off = 16; off > 0; off >>= 1) {
            s0 += __shfl_xor_sync(0xffffffffu, s0, off);
            s1 += __shfl_xor_sync(0xffffffffu, s1, off);
        }
        if (lane == 0) { g_pq[b * ATTN_ + r0] = s0; g_pq[b * ATTN_ + r1] = s1; }
    }
    __syncthreads();
}

// ---- conv task for step t (t>=1) ----
__device__ __forceinline__ void conv_task(const float* __restrict__ convw,
                                          float* __restrict__ out_align,
                                          int t, int idx, float* dsh) {
    int tid = threadIdx.x;
    float* h0 = dsh;
    float* h1 = dsh + 132;
    float* cv = dsh + 264;
    int b = idx >> 2, l0 = (idx & 3) * 100;
    int pp = (t - 1) & 1, pc = t & 1;
    float s = 0.f;
    #pragma unroll
    for (int i = 0; i < 8; ++i) s += __ldcg(&g_psum[pp][b * 8 + i]);
    float invS = 1.f / s;
    for (int j = tid; j < 130; j += NTHR) {
        int pos = l0 - 15 + j;
        float pv = 0.f, anew = 0.f;
        if (pos >= 0 && pos < L_) {
            pv = __ldcg(&g_p[b * L_ + pos]) * invS;
            anew = __ldcg(&g_A[pp][b * L_ + pos]) + pv;
            if (pos >= l0 && pos < l0 + 100) {
                g_A[pc][b * L_ + pos] = anew;
                out_align[((size_t)b * T_ + (t - 1)) * L_ + pos] = pv;
            }
        }
        h0[j] = pv; h1[j] = anew;
    }
    for (int i = tid; i < NFILT * 62; i += NTHR) cv[i] = convw[i];
    __syncthreads();
    int f = tid & 31, lr = tid >> 5;
    const float* cf0 = cv + f * 62;
    const float* cf1 = cf0 + 31;
    for (int l = l0 + lr; l < l0 + 100; l += 16) {
        int base = l - l0;
        float acc = 0.f;
        #pragma unroll
        for (int k = 0; k < 31; ++k)
            acc += h0[base + k] * cf0[k] + h1[base + k] * cf1[k];
        g_cl[((size_t)b * L_ + l) * NFILT + f] = acc;
    }
    __syncthreads();
}

// ---- energy + ctx partials for (b, 50-l tile) ----
__device__ __forceinline__ void energy_ctx_phase(
        const float* __restrict__ memory, const float* __restrict__ wloc,
        const float* __restrict__ av, int t, int blk, float* dsh) {
    int tid = threadIdx.x, lane = tid & 31, w = tid >> 5;
    int b = blk >> 3, tile = blk & 7, l0 = tile * 50;
    float* wlT = dsh;
    float* pqs = dsh + 4096;
    float* vs  = dsh + 4224;
    float* sp  = dsh + 4352;
    float* cls = dsh + 4416;
    float* red = dsh + 4928;
    for (int i = tid; i < ATTN_ * NFILT; i += NTHR)
        wlT[(i & 31) * ATTN_ + (i >> 5)] = wloc[i];
    if (tid < ATTN_) { pqs[tid] = __ldcg(&g_pq[b * ATTN_ + tid]); vs[tid] = av[tid]; }
    __syncthreads();
    float psum = 0.f;
    for (int l = l0 + w; l < l0 + 50; l += 16) {
        cls[w * 32 + lane] = __ldcg(&g_cl[((size_t)b * L_ + l) * NFILT + lane]);
        __syncwarp();
        const float* pmr = g_pm + ((size_t)b * L_ + l) * ATTN_;
        float s0 = pqs[lane]      + pmr[lane];
        float s1 = pqs[lane + 32] + pmr[lane + 32];
        float s2 = pqs[lane + 64] + pmr[lane + 64];
        float s3 = pqs[lane + 96] + pmr[lane + 96];
        #pragma unroll
        for (int f = 0; f < NFILT; ++f) {
            float clf = cls[w * 32 + f];
            const float* wr = wlT + f * ATTN_;
            s0 += clf * wr[lane];       s1 += clf * wr[lane + 32];
            s2 += clf * wr[lane + 64];  s3 += clf * wr[lane + 96];
        }
        float e = tanhf(s0) * vs[lane] + tanhf(s1) * vs[lane + 32] +
                  tanhf(s2) * vs[lane + 64] + tanhf(s3) * vs[lane + 96];
        #pragma unroll
        for (int off = 16; off > 0; off >>= 1) e += __shfl_xor_sync(0xffffffffu, e, off);
        if (lane == 0) {
            float p = expf(e);
            g_p[b * L_ + l] = p;
            sp[l - l0] = p;
            psum += p;
        }
        __syncwarp();
    }
    if (lane == 0) red[w] = psum;
    __syncthreads();
    if (tid == 0) {
        float s = 0.f;
        #pragma unroll
        for (int i = 0; i < 16; ++i) s += red[i];
        g_psum[t & 1][b * 8 + tile] = s;
    }
    int c = tid;
    const float* mp = memory + ((size_t)b * L_ + l0) * ENC + c;
    float acc = 0.f;
    #pragma unroll 10
    for (int j = 0; j < 50; ++j) acc += sp[j] * mp[(size_t)j * ENC];
    atomicAdd(&g_ctxraw[t & 1][b * ENC + c], acc);
    __syncthreads();
}

// ---- output projection for step tprev (3 blocks x 32 rows) ----
__device__ __forceinline__ void out_proj(
        const float* __restrict__ proj_w, const float* __restrict__ proj_b,
        const float* __restrict__ gate_w, const float* __restrict__ gate_b,
        int tprev, int blkL, float* __restrict__ out_mel, float* __restrict__ out_stop,
        float* shz) {
    int tid = threadIdx.x, lane = tid & 31, w = tid >> 5;
    int par = tprev & 1;
    if (tid < 16) {
        float s = 0.f;
        #pragma unroll
        for (int i = 0; i < 8; ++i) s += __ldcg(&g_psum[par][tid * 8 + i]);
        shz[960 + tid] = 1.f / s;
    }
    __syncthreads();
    const float* dh = g_dh[(tprev + 1) & 1];
    const float* cr = g_ctxraw[par];
    int r0 = blkL * 32 + w * 2;
    for (int rr = 0; rr < 2; ++rr) {
        int r = r0 + rr;
        if (r > 80) break;
        const float* wr = (r < 80) ? proj_w + (size_t)r * (QHD + ENC) : gate_w;
        float accA[16], accB[16];
        #pragma unroll
        for (int b = 0; b < 16; ++b) { accA[b] = 0.f; accB[b] = 0.f; }
        for (int ch = 0; ch < 8; ++ch) {
            int k = (ch << 7) + (lane << 2);
            float4 a = *(const float4*)(wr + k);
            #pragma unroll
            for (int b = 0; b < 16; ++b) {
                float4 xv = __ldcg((const float4*)(dh + b * QHD + k));
                accA[b] += a.x * xv.x + a.y * xv.y + a.z * xv.z + a.w * xv.w;
            }
        }
        for (int ch = 0; ch < 4; ++ch) {
            int k = (ch << 7) + (lane << 2);
            float4 a = *(const float4*)(wr + QHD + k);
            #pragma unroll
            for (int b = 0; b < 16; ++b) {
                float4 xv = __ldcg((const float4*)(cr + b * ENC + k));
                accB[b] += a.x * xv.x + a.y * xv.y + a.z * xv.z + a.w * xv.w;
            }
        }
        #pragma unroll
        for (int off = 16; off > 0; off >>= 1) {
            #pragma unroll
            for (int b = 0; b < 16; ++b) {
                accA[b] += __shfl_xor_sync(0xffffffffu, accA[b], off);
                accB[b] += __shfl_xor_sync(0xffffffffu, accB[b], off);
            }
        }
        if (lane < 16) {
            int b = lane;
            float val = accA[b] + accB[b] * shz[960 + b];
            if (r < 80) out_mel[((size_t)b * T_ + tprev) * NMELS + r] = val + proj_b[r];
            else        out_stop[(size_t)b * T_ + tprev] = sigmoidf_(val + gate_b[0]);
        }
    }
    __syncthreads();
}

__global__ __launch_bounds__(NTHR, 1) void decoder_kernel(
    const float* __restrict__ memory, const float* __restrict__ teacher,
    const float* __restrict__ pre_w1, const float* __restrict__ pre_w2,
    const float* __restrict__ q_wih, const float* __restrict__ q_whh,
    const float* __restrict__ q_bih, const float* __restrict__ q_bhh,
    const float* __restrict__ d_wih, const float* __restrict__ d_whh,
    const float* __restrict__ d_bih, const float* __restrict__ d_bhh,
    const float* __restrict__ wq, const float* __restrict__ conv,
    const float* __restrict__ wloc, const float* __restrict__ av,
    const float* __restrict__ wm,
    const float* __restrict__ proj_w, const float* __restrict__ proj_b,
    const float* __restrict__ gate_w, const float* __restrict__ gate_b,
    float* __restrict__ out_mel, float* __restrict__ out_align,
    float* __restrict__ out_stop) {
    extern __shared__ __align__(16) float dshf[];
    float2* xs2 = (float2*)dshf;
    __shared__ __align__(16) float shz[1024];
    float2* shz2 = (float2*)shz;
    int blk = blockIdx.x, tid = threadIdx.x;
    int nu = (blk < 136) ? 7 : 6;
    int u0 = (blk < 136) ? blk * 7 : 952 + (blk - 136) * 6;

    // ---- init ----
    for (int i = blk * NTHR + tid; i < B_ * QHD; i += NBLK * NTHR) {
        g_qh[0][i] = 0.f; g_qc[i] = 0.f; g_dh[0][i] = 0.f; g_dc[i] = 0.f;
    }
    for (int i = blk * NTHR + tid; i < B_ * ENC; i += NBLK * NTHR) {
        g_ctxraw[0][i] = 0.f; g_ctxraw[1][i] = 0.f;
    }
    for (int i = blk * NTHR + tid; i < B_ * L_; i += NBLK * NTHR) {
        g_A[0][i] = 0.f; g_A[1][i] = 0.f;
    }
    for (int i = blk * NTHR + tid; i < B_ * L_ * NFILT; i += NBLK * NTHR) g_cl[i] = 0.f;
    for (int i = blk * NTHR + tid; i < B_ * PRE; i += NBLK * NTHR) g_dec_ins[i] = 0.f;

    // ---- prenet layer 1 ----
    for (int tile = blk; tile < 200; tile += NBLK) {
        __syncthreads();
        int r0 = tile * 16;
        for (int i = tid; i < 16 * NMELS; i += NTHR) dshf[i] = teacher[(size_t)r0 * NMELS + i];
        __syncthreads();
        int j = tid & 255, rh = tid >> 8;
        const float* wr = pre_w1 + (size_t)j * NMELS;
        for (int r = rh * 8; r < rh * 8 + 8; ++r) {
            float acc = 0.f;
            #pragma unroll
            for (int m = 0; m < NMELS; ++m) acc += dshf[r * NMELS + m] * wr[m];
            g_h1[(size_t)(r0 + r) * PRE + j] = fmaxf(acc, 0.f);
        }
    }
    grid_sync();

    // ---- prenet layer 2 + processed_memory ----
    for (int tt = blk; tt < 199; tt += NBLK) {
        int t = tt + 1;
        __syncthreads();
        for (int i = tid; i < 16 * PRE; i += NTHR)
            dshf[i] = __ldcg(&g_h1[((size_t)(i >> 8) * T_ + (t - 1)) * PRE + (i & 255)]);
        __syncthreads();
        int j = tid & 255, rh = tid >> 8;
        const float4* wr4 = (const float4*)(pre_w2 + (size_t)j * PRE);
        for (int bb = rh * 8; bb < rh * 8 + 8; ++bb) {
            const float4* sx4 = (const float4*)(dshf + bb * PRE);
            float acc = 0.f;
            #pragma unroll 8
            for (int k = 0; k < PRE / 4; ++k) {
                float4 a = wr4[k], x = sx4[k];
                acc += a.x * x.x + a.y * x.y + a.z * x.z + a.w * x.w;
            }
            g_dec_ins[((size_t)t * B_ + bb) * PRE + j] = fmaxf(acc, 0.f);
        }
    }
    for (int tile = blk; tile < 400; tile += NBLK) {
        __syncthreads();
        int r0 = tile * 16;
        for (int i = tid; i < 16 * ENC; i += NTHR) dshf[i] = memory[(size_t)r0 * ENC + i];
        __syncthreads();
        int a = tid & 127, q = tid >> 7;
        const float4* wr4 = (const float4*)(wm + (size_t)a * ENC);
        for (int r = q * 4; r < q * 4 + 4; ++r) {
            const float4* sx4 = (const float4*)(dshf + r * ENC);
            float acc = 0.f;
            #pragma unroll 8
            for (int k = 0; k < ENC / 4; ++k) {
                float4 aa = wr4[k], x = sx4[k];
                acc += aa.x * x.x + aa.y * x.y + aa.z * x.z + aa.w * x.w;
            }
            g_pm[(size_t)(r0 + r) * ATTN_ + a] = acc;
        }
    }
    grid_sync();

    // ---- decode loop: 4 phases/step ----
    for (int t = 0; t < T_; ++t) {
        // P_A: qLSTM on all 148 blocks
        {
            if (t > 0) {
                if (tid < 16) {
                    float s = 0.f;
                    #pragma unroll
                    for (int i = 0; i < 8; ++i) s += __ldcg(&g_psum[(t + 1) & 1][tid * 8 + i]);
                    shz[960 + tid] = 1.f / s;
                }
                __syncthreads();
            }
            stage2(xs2, 1792, 0, g_dec_ins + (size_t)t * B_ * PRE, PRE, PRE);
            if (t > 0) stage2_scaled(xs2, 1792, 256, g_ctxraw[(t + 1) & 1], ENC, shz + 960);
            else       stage2_zero(xs2, 1792, 256, ENC);
            stage2(xs2, 1792, 768, g_qh[t & 1], QHD, QHD);
            __syncthreads();
            lstm2<6, 8>(xs2, 1792, 768, 384, q_wih, q_whh, q_bih, q_bhh,
                        g_qh[(t + 1) & 1], g_qc, u0, nu, shz2);
        }
        grid_sync();
        // P_B1: pq (0-31) | conv (32-95) | out_proj(t-1) (96-98)
        if (blk < 32) {
            pq_phase(wq, g_qh[(t + 1) & 1], blk, dshf);
        } else if (blk < 96) {
            if (t > 0) conv_task(conv, out_align, t, blk - 32, dshf);
        } else if (blk < 99) {
            if (t > 0) out_proj(proj_w, proj_b, gate_w, gate_b, t - 1, blk - 96,
                                out_mel, out_stop, shz);
        }
        grid_sync();
        // P_B2: energies + ctx partials
        if (blk < 128) energy_ctx_phase(memory, wloc, av, t, blk, dshf);
        grid_sync();
        // P_D: dLSTM on all 148 blocks (+ zero next ctxraw by spare warps)
        {
            if (blk < 16 && tid >= 448) {
                int i0 = blk * 512 + (tid - 448) * 8;
                #pragma unroll
                for (int k = 0; k < 8; ++k) g_ctxraw[(t + 1) & 1][i0 + k] = 0.f;
            }
            if (tid < 16) {
                float s = 0.f;
                #pragma unroll
                for (int i = 0; i < 8; ++i) s += __ldcg(&g_psum[t & 1][tid * 8 + i]);
                shz[960 + tid] = 1.f / s;
            }
            __syncthreads();
            stage2_scaled(xs2, 2560, 0, g_ctxraw[t & 1], ENC, shz + 960);
            stage2(xs2, 2560, 512,  g_qh[(t + 1) & 1], QHD, QHD);
            stage2(xs2, 2560, 1536, g_dh[t & 1], QHD, QHD);
            __syncthreads();
            lstm2<12, 8>(xs2, 2560, 1536, 768, d_wih, d_whh, d_bih, d_bhh,
                         g_dh[(t + 1) & 1], g_dc, u0, nu, shz2);
        }
        grid_sync();
    }
    // finals: out_proj(T-1) + alignments(T-1)
    if (blk >= 96 && blk < 99) {
        out_proj(proj_w, proj_b, gate_w, gate_b, T_ - 1, blk - 96,
                 out_mel, out_stop, shz);
    } else if (blk >= 32 && blk < 96) {
        int idx = blk - 32;
        int b = idx >> 2, l0 = (idx & 3) * 100;
        float s = 0.f;
        #pragma unroll
        for (int i = 0; i < 8; ++i) s += __ldcg(&g_psum[(T_ - 1) & 1][b * 8 + i]);
        float invS = 1.f / s;
        for (int j = tid; j < 100; j += NTHR) {
            int l = l0 + j;
            out_align[((size_t)b * T_ + (T_ - 1)) * L_ + l] = __ldcg(&g_p[b * L_ + l]) * invS;
        }
    }
}

extern "C" void kernel_launch(void* const* d_in, const int* in_sizes, int n_in,
                              void* d_out, int out_size) {
    (void)in_sizes; (void)n_in; (void)out_size;
    const float* memory  = (const float*)d_in[0];
    // d_in[1] memory_lengths unused (mask = None in reference)
    const float* teacher = (const float*)d_in[2];
    const float* pre_w1  = (const float*)d_in[3];
    const float* pre_w2  = (const float*)d_in[4];
    const float* q_wih   = (const float*)d_in[5];
    const float* q_whh   = (const float*)d_in[6];
    const float* q_bih   = (const float*)d_in[7];
    const float* q_bhh   = (const float*)d_in[8];
    const float* d_wih   = (const float*)d_in[9];
    const float* d_whh   = (const float*)d_in[10];
    const float* d_bih   = (const float*)d_in[11];
    const float* d_bhh   = (const float*)d_in[12];
    const float* attn_wq   = (const float*)d_in[13];
    const float* attn_wm   = (const float*)d_in[14];
    const float* attn_conv = (const float*)d_in[15];
    const float* attn_wloc = (const float*)d_in[16];
    const float* attn_v    = (const float*)d_in[17];
    const float* proj_w  = (const float*)d_in[18];
    const float* proj_b  = (const float*)d_in[19];
    const float* gate_w  = (const float*)d_in[20];
    const float* gate_b  = (const float*)d_in[21];

    float* out_mel   = (float*)d_out;
    float* out_align = out_mel + (size_t)B_ * T_ * NMELS;
    float* out_stop  = out_align + (size_t)B_ * T_ * L_;

    cudaFuncSetAttribute(decoder_kernel,
                         cudaFuncAttributeMaxDynamicSharedMemorySize, SMEM_BYTES);

    decoder_kernel<<<NBLK, NTHR, SMEM_BYTES>>>(
        memory, teacher, pre_w1, pre_w2,
        q_wih, q_whh, q_bih, q_bhh,
        d_wih, d_whh, d_bih, d_bhh,
        attn_wq, attn_conv, attn_wloc, attn_v, attn_wm,
        proj_w, proj_b, gate_w, gate_b,
        out_mel, out_align, out_stop);
}

// round 14
// speedup vs baseline: 1.3055x; 1.3055x over previous
#include <cuda_runtime.h>
#include <math.h>

#define B_    16
#define L_    400
#define T_    200
#define NMELS 80
#define ENC   512
#define PRE   256
#define QHD   1024
#define ATTN_ 128
#define NFILT 32
#define NBLK  148
#define NLSTM 128
#define NTHR  512
#define SMEM_BYTES 163840   // dLSTM packed staging: 8 pairs * 2560 * 8 B

typedef unsigned long long ull;

// ---- scratch (device globals; allocation forbidden) ----
__device__ __align__(16) float g_dec_ins[T_ * B_ * PRE];
__device__ __align__(16) float g_h1[B_ * T_ * PRE];
__device__ __align__(16) float g_pm[B_ * L_ * ATTN_];
__device__ __align__(16) float g_cl[B_ * L_ * NFILT];
__device__ __align__(16) float g_p[B_ * L_];          // exp(energy)
__device__ __align__(16) float g_psum[2][B_ * 8];     // per-tile partial sums
__device__ __align__(16) float g_pqpart[NLSTM * B_ * ATTN_]; // per-block pq partials
__device__ __align__(16) float g_wqT[QHD * ATTN_];    // wq transposed [u][a]
__device__ __align__(16) float g_ctxraw[2][B_ * ENC]; // unnormalized context
__device__ __align__(16) float g_A[2][B_ * L_];       // cumulative attention
__device__ __align__(16) float g_qh[2][B_ * QHD];
__device__ __align__(16) float g_qc[B_ * QHD];
__device__ __align__(16) float g_dh[2][B_ * QHD];
__device__ __align__(16) float g_dc[B_ * QHD];
__device__ unsigned g_arrive[NBLK];  // monotonic per-block arrival counters
__device__ unsigned g_gen;           // monotonic release counter

// ---- f32x2 helpers ----
__device__ __forceinline__ ull f2bcast(float a) {
    ull r; asm("mov.b64 %0, {%1, %1};" : "=l"(r) : "f"(a)); return r;
}
__device__ __forceinline__ ull fma2(ull x, ull w, ull c) {
    ull d; asm("fma.rn.f32x2 %0, %1, %2, %3;" : "=l"(d) : "l"(x), "l"(w), "l"(c)); return d;
}
__device__ __forceinline__ ull add2(ull a, ull b) {
    ull d; asm("add.rn.f32x2 %0, %1, %2;" : "=l"(d) : "l"(a), "l"(b)); return d;
}
__device__ __forceinline__ float2 unpack2(ull v) {
    float2 f; asm("mov.b64 {%0, %1}, %2;" : "=f"(f.x), "=f"(f.y) : "l"(v)); return f;
}

// ---- fast grid barrier: parallel arrivals + block-0 collector ----
__device__ __forceinline__ void grid_sync(unsigned& gen, int blk) {
    __syncthreads();
    ++gen;
    if (threadIdx.x == 0) {
        __threadfence();                       // drain my stores to L2
        atomicExch(&g_arrive[blk], gen);       // parallel: distinct addresses
    }
    if (blk == 0) {
        if (threadIdx.x < NBLK) {
            while ((int)(__ldcg(&g_arrive[threadIdx.x]) - gen) < 0) __nanosleep(32);
        }
        __syncthreads();
        if (threadIdx.x == 0) atomicExch(&g_gen, gen);
    } else {
        if (threadIdx.x == 0) {
            while ((int)(__ldcg(&g_gen) - gen) < 0) __nanosleep(64);
        }
        __syncthreads();
    }
}

__device__ __forceinline__ float sigmoidf_(float z) { return 1.f / (1.f + expf(-z)); }

// ---- stage 16 batches into packed f32x2 smem: xs2[pair p][k], pair = (b=p, b=p+8) ----
__device__ __forceinline__ void stage2(float2* xs2, int Kf2, int coff,
                                       const float* __restrict__ src, int glen, int len) {
    int n4 = len >> 2;
    for (int idx = threadIdx.x; idx < 8 * n4; idx += NTHR) {
        int p = idx / n4, k4 = (idx - p * n4) << 2;
        float4 lo = __ldcg((const float4*)(src + (size_t)p * glen + k4));
        float4 hi = __ldcg((const float4*)(src + (size_t)(p + 8) * glen + k4));
        float2* d = xs2 + (size_t)p * Kf2 + coff + k4;
        *(float4*)(d)     = make_float4(lo.x, hi.x, lo.y, hi.y);
        *(float4*)(d + 2) = make_float4(lo.z, hi.z, lo.w, hi.w);
    }
}
__device__ __forceinline__ void stage2_scaled(float2* xs2, int Kf2, int coff,
                                              const float* __restrict__ src, int len,
                                              const float* sinv) {
    int n4 = len >> 2;
    for (int idx = threadIdx.x; idx < 8 * n4; idx += NTHR) {
        int p = idx / n4, k4 = (idx - p * n4) << 2;
        float sl = sinv[p], sh = sinv[p + 8];
        float4 lo = __ldcg((const float4*)(src + (size_t)p * len + k4));
        float4 hi = __ldcg((const float4*)(src + (size_t)(p + 8) * len + k4));
        float2* d = xs2 + (size_t)p * Kf2 + coff + k4;
        *(float4*)(d)     = make_float4(lo.x * sl, hi.x * sh, lo.y * sl, hi.y * sh);
        *(float4*)(d + 2) = make_float4(lo.z * sl, hi.z * sh, lo.w * sl, hi.w * sh);
    }
}
__device__ __forceinline__ void stage2_zero(float2* xs2, int Kf2, int coff, int len) {
    int n4 = len >> 2;
    float4 z = make_float4(0.f, 0.f, 0.f, 0.f);
    for (int idx = threadIdx.x; idx < 8 * n4; idx += NTHR) {
        int p = idx / n4, k4 = (idx - p * n4) << 2;
        float2* d = xs2 + (size_t)p * Kf2 + coff + k4;
        *(float4*)(d) = z; *(float4*)(d + 2) = z;
    }
}

// ---- f32x2 gemv, conflict-free: lane covers cols (2*lane, 2*lane+1) per 64-col iter ----
template<int NC>
__device__ __forceinline__ void gemvf2c(const ull* __restrict__ xb, int Kf2,
                                        const float* __restrict__ w0,
                                        const float* __restrict__ w1,
                                        const float* __restrict__ w2,
                                        const float* __restrict__ w3,
                                        int lane, ull acc[4][8]) {
    int c0 = lane << 1;
    float2 wa = *(const float2*)(w0 + c0);
    float2 wb = *(const float2*)(w1 + c0);
    float2 wc = *(const float2*)(w2 + c0);
    float2 wd = *(const float2*)(w3 + c0);
    #pragma unroll
    for (int it = 0; it < NC; ++it) {
        float2 na, nb, nc2, nd;
        if (it + 1 < NC) {
            int cn = c0 + ((it + 1) << 6);
            na  = *(const float2*)(w0 + cn);
            nb  = *(const float2*)(w1 + cn);
            nc2 = *(const float2*)(w2 + cn);
            nd  = *(const float2*)(w3 + cn);
        } else {
            na = nb = nc2 = nd = make_float2(0.f, 0.f);
        }
        ull A0 = f2bcast(wa.x), A1 = f2bcast(wa.y);
        ull B0 = f2bcast(wb.x), B1 = f2bcast(wb.y);
        ull C0 = f2bcast(wc.x), C1 = f2bcast(wc.y);
        ull D0 = f2bcast(wd.x), D1 = f2bcast(wd.y);
        const ull* xp = xb + (it << 6) + c0;
        #pragma unroll
        for (int p = 0; p < 8; ++p) {
            longlong2 xv = *(const longlong2*)(xp + (size_t)p * Kf2);
            ull x0 = (ull)xv.x, x1 = (ull)xv.y;
            acc[0][p] = fma2(x0, A0, acc[0][p]);
            acc[1][p] = fma2(x0, B0, acc[1][p]);
            acc[2][p] = fma2(x0, C0, acc[2][p]);
            acc[3][p] = fma2(x0, D0, acc[3][p]);
            acc[0][p] = fma2(x1, A1, acc[0][p]);
            acc[1][p] = fma2(x1, B1, acc[1][p]);
            acc[2][p] = fma2(x1, C1, acc[2][p]);
            acc[3][p] = fma2(x1, D1, acc[3][p]);
        }
        wa = na; wb = nb; wc = nc2; wd = nd;
    }
}

// ---- LSTM phase: warp-pair per unit (lu = w>>1, K-half = w&1), all 4 gates;
//      optionally records h into sh_h[u*16+b] for pq partials ----
template<int NCIH, int NCHH>
__device__ __forceinline__ void lstm2(const float2* xs2, int Kf2, int kih, int ihHalf,
        const float* __restrict__ wih, const float* __restrict__ whh,
        const float* __restrict__ bih, const float* __restrict__ bhh,
        float* __restrict__ ho, float* __restrict__ cb, int u0, float2* shz2,
        float* sh_h) {
    int tid = threadIdx.x, lane = tid & 31, w = tid >> 5;
    int lu = w >> 1, h = w & 1;
    {
        int u = u0 + lu;
        ull acc[4][8];
        #pragma unroll
        for (int g = 0; g < 4; ++g)
            #pragma unroll
            for (int p = 0; p < 8; ++p) acc[g][p] = 0ull;
        gemvf2c<NCIH>((const ull*)xs2 + h * ihHalf, Kf2,
                      wih + (size_t)(0 * 1024 + u) * kih + h * ihHalf,
                      wih + (size_t)(1 * 1024 + u) * kih + h * ihHalf,
                      wih + (size_t)(2 * 1024 + u) * kih + h * ihHalf,
                      wih + (size_t)(3 * 1024 + u) * kih + h * ihHalf, lane, acc);
        gemvf2c<NCHH>((const ull*)xs2 + kih + h * 512, Kf2,
                      whh + (size_t)(0 * 1024 + u) * QHD + h * 512,
                      whh + (size_t)(1 * 1024 + u) * QHD + h * 512,
                      whh + (size_t)(2 * 1024 + u) * QHD + h * 512,
                      whh + (size_t)(3 * 1024 + u) * QHD + h * 512, lane, acc);
        #pragma unroll
        for (int g = 0; g < 4; ++g)
            #pragma unroll
            for (int p = 0; p < 8; ++p) {
                ull v = acc[g][p];
                #pragma unroll
                for (int off = 16; off > 0; off >>= 1)
                    v = add2(v, __shfl_xor_sync(0xffffffffu, v, off));
                acc[g][p] = v;
            }
        if (lane == 0) {
            float2* dst = shz2 + (lu * 2 + h) * 32;
            #pragma unroll
            for (int g = 0; g < 4; ++g)
                #pragma unroll
                for (int p = 0; p < 8; ++p) dst[g * 8 + p] = unpack2(acc[g][p]);
        }
    }
    __syncthreads();
    if (tid < 128) {
        int b = tid & 15, ui = tid >> 4, u = u0 + ui;
        int p = b & 7, hi8 = b >> 3;
        float z[4];
        #pragma unroll
        for (int g = 0; g < 4; ++g) {
            float2 a = shz2[(ui * 2 + 0) * 32 + g * 8 + p];
            float2 c2 = shz2[(ui * 2 + 1) * 32 + g * 8 + p];
            z[g] = (hi8 ? a.y : a.x) + (hi8 ? c2.y : c2.x)
                 + bih[g * 1024 + u] + bhh[g * 1024 + u];
        }
        float cc = sigmoidf_(z[1]) * cb[b * 1024 + u] + sigmoidf_(z[0]) * tanhf(z[2]);
        cb[b * 1024 + u] = cc;
        float hv = sigmoidf_(z[3]) * tanhf(cc);
        ho[b * 1024 + u] = hv;
        if (sh_h) sh_h[ui * 16 + b] = hv;
    }
    __syncthreads();
}

// ---- conv task for step t (t>=1) ----
__device__ __forceinline__ void conv_task(const float* __restrict__ convw,
                                          float* __restrict__ out_align,
                                          int t, int idx, float* dsh) {
    int tid = threadIdx.x;
    float* h0 = dsh;
    float* h1 = dsh + 132;
    float* cv = dsh + 264;
    int b = idx >> 2, l0 = (idx & 3) * 100;
    int pp = (t - 1) & 1, pc = t & 1;
    float s = 0.f;
    #pragma unroll
    for (int i = 0; i < 8; ++i) s += __ldcg(&g_psum[pp][b * 8 + i]);
    float invS = 1.f / s;
    __syncthreads();
    for (int j = tid; j < 130; j += NTHR) {
        int pos = l0 - 15 + j;
        float pv = 0.f, anew = 0.f;
        if (pos >= 0 && pos < L_) {
            pv = __ldcg(&g_p[b * L_ + pos]) * invS;
            anew = __ldcg(&g_A[pp][b * L_ + pos]) + pv;
            if (pos >= l0 && pos < l0 + 100) {
                g_A[pc][b * L_ + pos] = anew;
                out_align[((size_t)b * T_ + (t - 1)) * L_ + pos] = pv;
            }
        }
        h0[j] = pv; h1[j] = anew;
    }
    for (int i = tid; i < NFILT * 62; i += NTHR) cv[i] = convw[i];
    __syncthreads();
    int f = tid & 31, lr = tid >> 5;
    const float* cf0 = cv + f * 62;
    const float* cf1 = cf0 + 31;
    for (int l = l0 + lr; l < l0 + 100; l += 16) {
        int base = l - l0;
        float acc = 0.f;
        #pragma unroll
        for (int k = 0; k < 31; ++k)
            acc += h0[base + k] * cf0[k] + h1[base + k] * cf1[k];
        g_cl[((size_t)b * L_ + l) * NFILT + f] = acc;
    }
    __syncthreads();
}

// ---- energy + ctx partials for (b, 50-l tile); pq summed from per-block partials ----
__device__ __forceinline__ void energy_ctx_phase(
        const float* __restrict__ memory, const float* __restrict__ wloc,
        const float* __restrict__ av, int t, int blk, float* dsh) {
    int tid = threadIdx.x, lane = tid & 31, w = tid >> 5;
    int b = blk >> 3, tile = blk & 7, l0 = tile * 50;
    float* wlT = dsh;            // 4096 [f][a]
    float* pqs = dsh + 4096;     // 128
    float* vs  = dsh + 4224;     // 128
    float* sp  = dsh + 4352;     // 64
    float* cls = dsh + 4416;     // 16 x 32
    float* red = dsh + 4928;     // 16
    float* sred = dsh + 4992;    // 512
    // reduce pq partials: pq[b][a] = sum over 128 LSTM blocks
    {
        int a = tid & 127, ch = tid >> 7;
        float s = 0.f;
        const float* src = g_pqpart + (size_t)(ch * 32) * 2048 + b * 128 + a;
        #pragma unroll 8
        for (int kb = 0; kb < 32; ++kb) s += __ldcg(src + (size_t)kb * 2048);
        sred[ch * 128 + a] = s;
    }
    for (int i = tid; i < ATTN_ * NFILT; i += NTHR)
        wlT[(i & 31) * ATTN_ + (i >> 5)] = wloc[i];
    if (tid < ATTN_) vs[tid] = av[tid];
    __syncthreads();
    if (tid < 128) pqs[tid] = sred[tid] + sred[128 + tid] + sred[256 + tid] + sred[384 + tid];
    __syncthreads();
    float psum = 0.f;
    for (int l = l0 + w; l < l0 + 50; l += 16) {
        cls[w * 32 + lane] = __ldcg(&g_cl[((size_t)b * L_ + l) * NFILT + lane]);
        __syncwarp();
        const float* pmr = g_pm + ((size_t)b * L_ + l) * ATTN_;
        float s0 = pqs[lane]      + pmr[lane];
        float s1 = pqs[lane + 32] + pmr[lane + 32];
        float s2 = pqs[lane + 64] + pmr[lane + 64];
        float s3 = pqs[lane + 96] + pmr[lane + 96];
        #pragma unroll
        for (int f = 0; f < NFILT; ++f) {
            float clf = cls[w * 32 + f];
            const float* wr = wlT + f * ATTN_;
            s0 += clf * wr[lane];       s1 += clf * wr[lane + 32];
            s2 += clf * wr[lane + 64];  s3 += clf * wr[lane + 96];
        }
        float e = tanhf(s0) * vs[lane] + tanhf(s1) * vs[lane + 32] +
                  tanhf(s2) * vs[lane + 64] + tanhf(s3) * vs[lane + 96];
        #pragma unroll
        for (int off = 16; off > 0; off >>= 1) e += __shfl_xor_sync(0xffffffffu, e, off);
        if (lane == 0) {
            float p = expf(e);            // |e| <= sum|v| ~ 5: safe without max-sub
            g_p[b * L_ + l] = p;
            sp[l - l0] = p;
            psum += p;
        }
        __syncwarp();
    }
    if (lane == 0) red[w] = psum;
    __syncthreads();
    if (tid == 0) {
        float s = 0.f;
        #pragma unroll
        for (int i = 0; i < 16; ++i) s += red[i];
        g_psum[t & 1][b * 8 + tile] = s;
    }
    int c = tid;
    const float* mp = memory + ((size_t)b * L_ + l0) * ENC + c;
    float acc = 0.f;
    #pragma unroll 10
    for (int j = 0; j < 50; ++j) acc += sp[j] * mp[(size_t)j * ENC];
    atomicAdd(&g_ctxraw[t & 1][b * ENC + c], acc);
    __syncthreads();
}

// ---- output projection for step tprev (3 blocks x 32 rows) ----
__device__ __forceinline__ void out_proj(
        const float* __restrict__ proj_w, const float* __restrict__ proj_b,
        const float* __restrict__ gate_w, const float* __restrict__ gate_b,
        int tprev, int blkL, float* __restrict__ out_mel, float* __restrict__ out_stop,
        float* shz) {
    int tid = threadIdx.x, lane = tid & 31, w = tid >> 5;
    int par = tprev & 1;
    if (tid < 16) {
        float s = 0.f;
        #pragma unroll
        for (int i = 0; i < 8; ++i) s += __ldcg(&g_psum[par][tid * 8 + i]);
        shz[960 + tid] = 1.f / s;
    }
    __syncthreads();
    const float* dh = g_dh[(tprev + 1) & 1];
    const float* cr = g_ctxraw[par];
    int r0 = blkL * 32 + w * 2;
    for (int rr = 0; rr < 2; ++rr) {
        int r = r0 + rr;
        if (r > 80) break;
        const float* wr = (r < 80) ? proj_w + (size_t)r * (QHD + ENC) : gate_w;
        float accA[16], accB[16];
        #pragma unroll
        for (int b = 0; b < 16; ++b) { accA[b] = 0.f; accB[b] = 0.f; }
        for (int ch = 0; ch < 8; ++ch) {
            int k = (ch << 7) + (lane << 2);
            float4 a = *(const float4*)(wr + k);
            #pragma unroll
            for (int b = 0; b < 16; ++b) {
                float4 xv = __ldcg((const float4*)(dh + b * QHD + k));
                accA[b] += a.x * xv.x + a.y * xv.y + a.z * xv.z + a.w * xv.w;
            }
        }
        for (int ch = 0; ch < 4; ++ch) {
            int k = (ch << 7) + (lane << 2);
            float4 a = *(const float4*)(wr + QHD + k);
            #pragma unroll
            for (int b = 0; b < 16; ++b) {
                float4 xv = __ldcg((const float4*)(cr + b * ENC + k));
                accB[b] += a.x * xv.x + a.y * xv.y + a.z * xv.z + a.w * xv.w;
            }
        }
        #pragma unroll
        for (int off = 16; off > 0; off >>= 1) {
            #pragma unroll
            for (int b = 0; b < 16; ++b) {
                accA[b] += __shfl_xor_sync(0xffffffffu, accA[b], off);
                accB[b] += __shfl_xor_sync(0xffffffffu, accB[b], off);
            }
        }
        if (lane < 16) {
            int b = lane;
            float val = accA[b] + accB[b] * shz[960 + b];
            if (r < 80) out_mel[((size_t)b * T_ + tprev) * NMELS + r] = val + proj_b[r];
            else        out_stop[(size_t)b * T_ + tprev] = sigmoidf_(val + gate_b[0]);
        }
    }
    __syncthreads();
}

__global__ __launch_bounds__(NTHR, 1) void decoder_kernel(
    const float* __restrict__ memory, const float* __restrict__ teacher,
    const float* __restrict__ pre_w1, const float* __restrict__ pre_w2,
    const float* __restrict__ q_wih, const float* __restrict__ q_whh,
    const float* __restrict__ q_bih, const float* __restrict__ q_bhh,
    const float* __restrict__ d_wih, const float* __restrict__ d_whh,
    const float* __restrict__ d_bih, const float* __restrict__ d_bhh,
    const float* __restrict__ wq, const float* __restrict__ conv,
    const float* __restrict__ wloc, const float* __restrict__ av,
    const float* __restrict__ wm,
    const float* __restrict__ proj_w, const float* __restrict__ proj_b,
    const float* __restrict__ gate_w, const float* __restrict__ gate_b,
    float* __restrict__ out_mel, float* __restrict__ out_align,
    float* __restrict__ out_stop) {
    extern __shared__ __align__(16) float dshf[];
    float2* xs2 = (float2*)dshf;
    float* sh_h = dshf + 28672;            // after qLSTM staging (28672 floats)
    __shared__ __align__(16) float shz[1024];
    __shared__ float s_inv[16];
    float2* shz2 = (float2*)shz;
    int blk = blockIdx.x, tid = threadIdx.x;
    unsigned bar_gen = __ldcg(&g_gen);     // stable pre-run value (all blocks equal)
    int u0 = blk * 8;                      // LSTM unit base for blk < 128

    // ---- init ----
    for (int i = blk * NTHR + tid; i < B_ * QHD; i += NBLK * NTHR) {
        g_qh[0][i] = 0.f; g_qc[i] = 0.f; g_dh[0][i] = 0.f; g_dc[i] = 0.f;
    }
    for (int i = blk * NTHR + tid; i < B_ * ENC; i += NBLK * NTHR) {
        g_ctxraw[0][i] = 0.f; g_ctxraw[1][i] = 0.f;
    }
    for (int i = blk * NTHR + tid; i < B_ * L_; i += NBLK * NTHR) {
        g_A[0][i] = 0.f; g_A[1][i] = 0.f;
    }
    for (int i = blk * NTHR + tid; i < B_ * L_ * NFILT; i += NBLK * NTHR) g_cl[i] = 0.f;
    for (int i = blk * NTHR + tid; i < B_ * PRE; i += NBLK * NTHR) g_dec_ins[i] = 0.f;
    for (int i = blk * NTHR + tid; i < QHD * ATTN_; i += NBLK * NTHR) {
        int u = i >> 7, a = i & 127;
        g_wqT[i] = wq[(size_t)a * QHD + u];
    }

    // ---- prenet layer 1 ----
    for (int tile = blk; tile < 200; tile += NBLK) {
        __syncthreads();
        int r0 = tile * 16;
        for (int i = tid; i < 16 * NMELS; i += NTHR) dshf[i] = teacher[(size_t)r0 * NMELS + i];
        __syncthreads();
        int j = tid & 255, rh = tid >> 8;
        const float* wr = pre_w1 + (size_t)j * NMELS;
        for (int r = rh * 8; r < rh * 8 + 8; ++r) {
            float acc = 0.f;
            #pragma unroll
            for (int m = 0; m < NMELS; ++m) acc += dshf[r * NMELS + m] * wr[m];
            g_h1[(size_t)(r0 + r) * PRE + j] = fmaxf(acc, 0.f);
        }
    }
    grid_sync(bar_gen, blk);

    // ---- prenet layer 2 + processed_memory ----
    for (int tt = blk; tt < 199; tt += NBLK) {
        int t = tt + 1;
        __syncthreads();
        for (int i = tid; i < 16 * PRE; i += NTHR)
            dshf[i] = __ldcg(&g_h1[((size_t)(i >> 8) * T_ + (t - 1)) * PRE + (i & 255)]);
        __syncthreads();
        int j = tid & 255, rh = tid >> 8;
        const float4* wr4 = (const float4*)(pre_w2 + (size_t)j * PRE);
        for (int bb = rh * 8; bb < rh * 8 + 8; ++bb) {
            const float4* sx4 = (const float4*)(dshf + bb * PRE);
            float acc = 0.f;
            #pragma unroll 8
            for (int k = 0; k < PRE / 4; ++k) {
                float4 a = wr4[k], x = sx4[k];
                acc += a.x * x.x + a.y * x.y + a.z * x.z + a.w * x.w;
            }
            g_dec_ins[((size_t)t * B_ + bb) * PRE + j] = fmaxf(acc, 0.f);
        }
    }
    for (int tile = blk; tile < 400; tile += NBLK) {
        __syncthreads();
        int r0 = tile * 16;
        for (int i = tid; i < 16 * ENC; i += NTHR) dshf[i] = memory[(size_t)r0 * ENC + i];
        __syncthreads();
        int a = tid & 127, q = tid >> 7;
        const float4* wr4 = (const float4*)(wm + (size_t)a * ENC);
        for (int r = q * 4; r < q * 4 + 4; ++r) {
            const float4* sx4 = (const float4*)(dshf + r * ENC);
            float acc = 0.f;
            #pragma unroll 8
            for (int k = 0; k < ENC / 4; ++k) {
                float4 aa = wr4[k], x = sx4[k];
                acc += aa.x * x.x + aa.y * x.y + aa.z * x.z + aa.w * x.w;
            }
            g_pm[(size_t)(r0 + r) * ATTN_ + a] = acc;
        }
    }
    grid_sync(bar_gen, blk);

    // ---- decode loop: 3 phases/step ----
    for (int t = 0; t < T_; ++t) {
        // P_A: qLSTM + pq partials (0..127) | out_proj(t-1) (128..130) | conv (131..147)
        if (blk < NLSTM) {
            if (t > 0) {
                if (tid < 16) {
                    float s = 0.f;
                    #pragma unroll
                    for (int i = 0; i < 8; ++i) s += __ldcg(&g_psum[(t + 1) & 1][tid * 8 + i]);
                    s_inv[tid] = 1.f / s;
                }
                __syncthreads();
            }
            stage2(xs2, 1792, 0, g_dec_ins + (size_t)t * B_ * PRE, PRE, PRE);
            if (t > 0) stage2_scaled(xs2, 1792, 256, g_ctxraw[(t + 1) & 1], ENC, s_inv);
            else       stage2_zero(xs2, 1792, 256, ENC);
            stage2(xs2, 1792, 768, g_qh[t & 1], QHD, QHD);
            __syncthreads();
            lstm2<6, 8>(xs2, 1792, 768, 384, q_wih, q_whh, q_bih, q_bhh,
                        g_qh[(t + 1) & 1], g_qc, u0, shz2, sh_h);
            // pq partials for this block's 8 units
            {
                int a = tid & 127, bq = tid >> 7;
                float a0 = 0.f, a1 = 0.f, a2 = 0.f, a3 = 0.f;
                #pragma unroll
                for (int u = 0; u < 8; ++u) {
                    float wv = g_wqT[(size_t)(u0 + u) * 128 + a];
                    const float* hh = sh_h + u * 16 + bq * 4;
                    a0 += wv * hh[0]; a1 += wv * hh[1];
                    a2 += wv * hh[2]; a3 += wv * hh[3];
                }
                float* dst = g_pqpart + (size_t)blk * 2048 + a;
                dst[(bq * 4 + 0) * 128] = a0;
                dst[(bq * 4 + 1) * 128] = a1;
                dst[(bq * 4 + 2) * 128] = a2;
                dst[(bq * 4 + 3) * 128] = a3;
            }
        } else if (blk < 131) {
            if (t > 0) out_proj(proj_w, proj_b, gate_w, gate_b, t - 1, blk - 128,
                                out_mel, out_stop, shz);
        } else {
            if (t > 0)
                for (int idx = blk - 131; idx < 64; idx += 17)
                    conv_task(conv, out_align, t, idx, dshf);
        }
        grid_sync(bar_gen, blk);
        // P_B: energies + ctx partials (128 blocks)
        if (blk < NLSTM) energy_ctx_phase(memory, wloc, av, t, blk, dshf);
        grid_sync(bar_gen, blk);
        // P_C: dLSTM (0..127) | zero next ctxraw (128..143)
        if (blk < NLSTM) {
            if (tid < 16) {
                float s = 0.f;
                #pragma unroll
                for (int i = 0; i < 8; ++i) s += __ldcg(&g_psum[t & 1][tid * 8 + i]);
                s_inv[tid] = 1.f / s;
            }
            __syncthreads();
            stage2_scaled(xs2, 2560, 0, g_ctxraw[t & 1], ENC, s_inv);
            stage2(xs2, 2560, 512,  g_qh[(t + 1) & 1], QHD, QHD);
            stage2(xs2, 2560, 1536, g_dh[t & 1], QHD, QHD);
            __syncthreads();
            lstm2<12, 8>(xs2, 2560, 1536, 768, d_wih, d_whh, d_bih, d_bhh,
                         g_dh[(t + 1) & 1], g_dc, u0, shz2, (float*)0);
        } else if (blk < 144) {
            int i0 = (blk - 128) * 512 + tid;
            g_ctxraw[(t + 1) & 1][i0] = 0.f;
        }
        grid_sync(bar_gen, blk);
    }
    // finals: out_proj(T-1) + alignments(T-1)
    if (blk >= 128 && blk < 131) {
        out_proj(proj_w, proj_b, gate_w, gate_b, T_ - 1, blk - 128,
                 out_mel, out_stop, shz);
    } else if (blk < 64) {
        int b = blk >> 2, l0 = (blk & 3) * 100;
        float s = 0.f;
        #pragma unroll
        for (int i = 0; i < 8; ++i) s += __ldcg(&g_psum[(T_ - 1) & 1][b * 8 + i]);
        float invS = 1.f / s;
        for (int j = tid; j < 100; j += NTHR) {
            int l = l0 + j;
            out_align[((size_t)b * T_ + (T_ - 1)) * L_ + l] = __ldcg(&g_p[b * L_ + l]) * invS;
        }
    }
}

extern "C" void kernel_launch(void* const* d_in, const int* in_sizes, int n_in,
                              void* d_out, int out_size) {
    (void)in_sizes; (void)n_in; (void)out_size;
    const float* memory  = (const float*)d_in[0];
    // d_in[1] memory_lengths unused (mask = None in reference)
    const float* teacher = (const float*)d_in[2];
    const float* pre_w1  = (const float*)d_in[3];
    const float* pre_w2  = (const float*)d_in[4];
    const float* q_wih   = (const float*)d_in[5];
    const float* q_whh   = (const float*)d_in[6];
    const float* q_bih   = (const float*)d_in[7];
    const float* q_bhh   = (const float*)d_in[8];
    const float* d_wih   = (const float*)d_in[9];
    const float* d_whh   = (const float*)d_in[10];
    const float* d_bih   = (const float*)d_in[11];
    const float* d_bhh   = (const float*)d_in[12];
    const float* attn_wq   = (const float*)d_in[13];
    const float* attn_wm   = (const float*)d_in[14];
    const float* attn_conv = (const float*)d_in[15];
    const float* attn_wloc = (const float*)d_in[16];
    const float* attn_v    = (const float*)d_in[17];
    const float* proj_w  = (const float*)d_in[18];
    const float* proj_b  = (const float*)d_in[19];
    const float* gate_w  = (const float*)d_in[20];
    const float* gate_b  = (const float*)d_in[21];

    float* out_mel   = (float*)d_out;
    float* out_align = out_mel + (size_t)B_ * T_ * NMELS;
    float* out_stop  = out_align + (size_t)B_ * T_ * L_;

    cudaFuncSetAttribute(decoder_kernel,
                         cudaFuncAttributeMaxDynamicSharedMemorySize, SMEM_BYTES);

    decoder_kernel<<<NBLK, NTHR, SMEM_BYTES>>>(
        memory, teacher, pre_w1, pre_w2,
        q_wih, q_whh, q_bih, q_bhh,
        d_wih, d_whh, d_bih, d_bhh,
        attn_wq, attn_conv, attn_wloc, attn_v, attn_wm,
        proj_w, proj_b, gate_w, gate_b,
        out_mel, out_align, out_stop);
}